// round 5
// baseline (speedup 1.0000x reference)
#include <cuda_runtime.h>
#include <cuda_bf16.h>

// Problem constants
#define B_  8
#define S_  128
#define E_  768
#define H_  12
#define D_  64
#define SD_ 8192          // S*D
#define BSROWS 1024       // B*S
#define QKROWS 192        // 2*B*H  (q rows 0..95, k rows 96..191)

// GEMM tiling
#define BM 64
#define BN 128
#define BK 16
#define TM 4
#define TN 8
// 256 threads = 16(x,n) * 16(y,m)

// ---------------- device scratch (static allocations only) ----------------
__device__ float g_qkf[QKROWS * SD_];   // q/k proj in rotated layout [192, 8192]  (6 MB)
__device__ float g_qkr[QKROWS * SD_];   // rotated q/k                 [192, 8192]  (6 MB)
__device__ float g_v  [BSROWS * E_];    // v proj   [1024, 768]                     (3 MB)
__device__ float g_ctx[BSROWS * E_];    // ctx in [B][H][S][D] order == [1024,768]  (3 MB)

// ---------------- generic fp32 SGEMM core ----------------
// C[M,N] = A[M,K] * op(B), A row-major.
// TRANSB=false: B is [K,N] row-major (used for X @ R)
// TRANSB=true : B is [N,K] row-major (used for X @ W^T)
// epi=0: plain row-major store into C
// epi=1: qk-scatter: row r(=b*128+s), col m(=h*64+d) -> C[(base + b*12 + h)*8192 + s*64 + d]
template<bool TRANSB>
__device__ __forceinline__ void sgemm_core(
    const float* __restrict__ A, const float* __restrict__ B, float* __restrict__ C,
    int N, int K, int epi, int scatter_base)
{
    __shared__ float As[2][BK][BM];
    __shared__ float Bs[2][BK][BN];

    const int tid = threadIdx.x;
    const int tx  = tid & 15;          // n direction
    const int ty  = tid >> 4;          // m direction
    const size_t bm = (size_t)blockIdx.y * BM;
    const size_t bn = (size_t)blockIdx.x * BN;

    // A tile loader: one float4 per thread, [64 rows x 16 k]
    const int arow = tid >> 2;            // 0..63
    const int acol = (tid & 3) << 2;      // 0,4,8,12
    const float* Ap = A + (bm + arow) * (size_t)K + acol;

    // B tile loader: two float4 per thread
    int br0, bc0, br1, bc1;
    const float *Bp0, *Bp1;
    if (!TRANSB) {
        const int f0 = tid * 2, f1 = f0 + 1;
        br0 = f0 >> 5; bc0 = (f0 & 31) << 2;   // k-row, n-col
        br1 = f1 >> 5; bc1 = (f1 & 31) << 2;
        Bp0 = B + (size_t)br0 * N + bn + bc0;
        Bp1 = B + (size_t)br1 * N + bn + bc1;
    } else {
        const int f0 = tid * 2, f1 = f0 + 1;
        br0 = f0 >> 2; bc0 = (f0 & 3) << 2;    // n-row, k-col
        br1 = f1 >> 2; bc1 = (f1 & 3) << 2;
        Bp0 = B + (bn + br0) * (size_t)K + bc0;
        Bp1 = B + (bn + br1) * (size_t)K + bc1;
    }

    float acc[TM][TN];
    #pragma unroll
    for (int i = 0; i < TM; i++)
        #pragma unroll
        for (int j = 0; j < TN; j++) acc[i][j] = 0.0f;

    // prologue: tile 0 -> buffer 0
    {
        const float4 ra  = *(const float4*)Ap;
        const float4 rb0 = *(const float4*)Bp0;
        const float4 rb1 = *(const float4*)Bp1;
        As[0][acol + 0][arow] = ra.x;
        As[0][acol + 1][arow] = ra.y;
        As[0][acol + 2][arow] = ra.z;
        As[0][acol + 3][arow] = ra.w;
        if (!TRANSB) {
            *(float4*)&Bs[0][br0][bc0] = rb0;
            *(float4*)&Bs[0][br1][bc1] = rb1;
        } else {
            Bs[0][bc0 + 0][br0] = rb0.x; Bs[0][bc0 + 1][br0] = rb0.y;
            Bs[0][bc0 + 2][br0] = rb0.z; Bs[0][bc0 + 3][br0] = rb0.w;
            Bs[0][bc1 + 0][br1] = rb1.x; Bs[0][bc1 + 1][br1] = rb1.y;
            Bs[0][bc1 + 2][br1] = rb1.z; Bs[0][bc1 + 3][br1] = rb1.w;
        }
    }
    __syncthreads();

    const int nt = K / BK;
    for (int t = 0; t < nt; ++t) {
        const int buf = t & 1;
        float4 ra, rb0, rb1;
        const bool hasNext = (t + 1 < nt);
        if (hasNext) {
            const size_t koff = (size_t)(t + 1) * BK;
            ra = *(const float4*)(Ap + koff);
            if (!TRANSB) {
                rb0 = *(const float4*)(Bp0 + koff * N);
                rb1 = *(const float4*)(Bp1 + koff * N);
            } else {
                rb0 = *(const float4*)(Bp0 + koff);
                rb1 = *(const float4*)(Bp1 + koff);
            }
        }

        #pragma unroll
        for (int kk = 0; kk < BK; ++kk) {
            const float4 av  = *(const float4*)&As[buf][kk][ty * TM];
            const float4 bv0 = *(const float4*)&Bs[buf][kk][tx * TN];
            const float4 bv1 = *(const float4*)&Bs[buf][kk][tx * TN + 4];
            const float a[TM]  = {av.x, av.y, av.z, av.w};
            const float bb[TN] = {bv0.x, bv0.y, bv0.z, bv0.w,
                                  bv1.x, bv1.y, bv1.z, bv1.w};
            #pragma unroll
            for (int i = 0; i < TM; i++)
                #pragma unroll
                for (int j = 0; j < TN; j++)
                    acc[i][j] = fmaf(a[i], bb[j], acc[i][j]);
        }

        if (hasNext) {
            const int nb = buf ^ 1;
            As[nb][acol + 0][arow] = ra.x;
            As[nb][acol + 1][arow] = ra.y;
            As[nb][acol + 2][arow] = ra.z;
            As[nb][acol + 3][arow] = ra.w;
            if (!TRANSB) {
                *(float4*)&Bs[nb][br0][bc0] = rb0;
                *(float4*)&Bs[nb][br1][bc1] = rb1;
            } else {
                Bs[nb][bc0 + 0][br0] = rb0.x; Bs[nb][bc0 + 1][br0] = rb0.y;
                Bs[nb][bc0 + 2][br0] = rb0.z; Bs[nb][bc0 + 3][br0] = rb0.w;
                Bs[nb][bc1 + 0][br1] = rb1.x; Bs[nb][bc1 + 1][br1] = rb1.y;
                Bs[nb][bc1 + 2][br1] = rb1.z; Bs[nb][bc1 + 3][br1] = rb1.w;
            }
        }
        __syncthreads();
    }

    // epilogue
    if (epi == 0) {
        #pragma unroll
        for (int i = 0; i < TM; i++) {
            float* cp = C + (bm + ty * TM + i) * (size_t)N + bn + tx * TN;
            *(float4*)(cp)     = make_float4(acc[i][0], acc[i][1], acc[i][2], acc[i][3]);
            *(float4*)(cp + 4) = make_float4(acc[i][4], acc[i][5], acc[i][6], acc[i][7]);
        }
    } else {
        #pragma unroll
        for (int i = 0; i < TM; i++) {
            const int r  = (int)bm + ty * TM + i;      // 0..1023
            const int bb_ = r >> 7;                    // batch
            const int s   = r & 127;
            const int m   = (int)bn + tx * TN;         // 0..767, multiple of 8
            const int h   = m >> 6;
            const int d   = m & 63;
            float* cp = C + (((size_t)(scatter_base + bb_ * H_ + h)) << 13) + s * D_ + d;
            *(float4*)(cp)     = make_float4(acc[i][0], acc[i][1], acc[i][2], acc[i][3]);
            *(float4*)(cp + 4) = make_float4(acc[i][4], acc[i][5], acc[i][6], acc[i][7]);
        }
    }
}

// ---------------- kernels ----------------

// Fused QKV projection: grid (6, 16, 3); z selects W and epilogue.
__global__ __launch_bounds__(256, 2)
void proj_kernel(const float* __restrict__ X,
                 const float* __restrict__ Wq,
                 const float* __restrict__ Wk,
                 const float* __restrict__ Wv)
{
    const float* W;
    float* Cc;
    int epi, base;
    if (blockIdx.z == 0)      { W = Wq; Cc = g_qkf; epi = 1; base = 0;  }
    else if (blockIdx.z == 1) { W = Wk; Cc = g_qkf; epi = 1; base = 96; }
    else                      { W = Wv; Cc = g_v;   epi = 0; base = 0;  }
    sgemm_core<true>(X, W, Cc, E_, E_, epi, base);
}

// Rotation: [192, 8192] @ R[8192, 8192] ; grid (64, 3)
__global__ __launch_bounds__(256, 2)
void rot_kernel(const float* __restrict__ R)
{
    sgemm_core<false>(g_qkf, R, g_qkr, SD_, SD_, 0, 0);
}

// Output projection: ctx[1024,768] @ Wo^T ; grid (6, 16)
__global__ __launch_bounds__(256, 2)
void final_kernel(const float* __restrict__ Wo, float* __restrict__ out)
{
    sgemm_core<true>(g_ctx, Wo, out, E_, E_, 0, 0);
}

// Per-(b,s) head-axis attention. grid 1024, block 192 (>= H*H = 144!).
#define ATTN_THREADS 192
__global__ __launch_bounds__(ATTN_THREADS)
void attn_kernel(const float* __restrict__ mask,
                 float* __restrict__ attn_out,
                 int write_attn)
{
    const int bs = blockIdx.x;
    const int b  = bs >> 7;
    const int s  = bs & 127;
    const int tid = threadIdx.x;

    __shared__ float qs[H_ * D_];
    __shared__ float ks[H_ * D_];
    __shared__ float vs[H_ * D_];
    __shared__ float aw[H_ * H_];

    for (int i = tid; i < H_ * D_; i += ATTN_THREADS) {
        const int h = i >> 6, d = i & 63;
        qs[i] = g_qkr[(((size_t)(b * H_ + h)) << 13) + s * D_ + d];
        ks[i] = g_qkr[(((size_t)(96 + b * H_ + h)) << 13) + s * D_ + d];
        vs[i] = g_v[(size_t)bs * E_ + i];
    }
    __syncthreads();

    // All 144 score entries computed (tid 0..143 active; block has 192 threads)
    if (tid < H_ * H_) {
        const int h = tid / H_, g = tid % H_;
        float acc = 0.0f;
        #pragma unroll
        for (int d = 0; d < D_; d++) acc += qs[h * D_ + d] * ks[g * D_ + d];
        aw[tid] = acc * 0.125f + mask[b * (H_ * H_) + tid];   // D^-0.5 = 1/8
    }
    __syncthreads();

    if (tid < H_) {
        float mx = -3.0e38f;
        #pragma unroll
        for (int g = 0; g < H_; g++) mx = fmaxf(mx, aw[tid * H_ + g]);
        float e[H_];
        float sum = 0.0f;
        #pragma unroll
        for (int g = 0; g < H_; g++) { e[g] = expf(aw[tid * H_ + g] - mx); sum += e[g]; }
        const float inv = 1.0f / sum;
        #pragma unroll
        for (int g = 0; g < H_; g++) aw[tid * H_ + g] = e[g] * inv;
    }
    __syncthreads();

    if (write_attn && tid < H_ * H_)
        attn_out[(size_t)bs * (H_ * H_) + tid] = aw[tid];

    // ctx[b][h][s][d] = sum_g aw[h][g] * v[b][s][g][d]   (stored [B,H,S,D] flat)
    for (int i = tid; i < H_ * D_; i += ATTN_THREADS) {
        const int h = i >> 6, d = i & 63;
        float acc = 0.0f;
        #pragma unroll
        for (int g = 0; g < H_; g++) acc += aw[h * H_ + g] * vs[g * D_ + d];
        g_ctx[(size_t)b * (H_ * S_ * D_) + h * (S_ * D_) + s * D_ + d] = acc;
    }
}

// ---------------- launch ----------------
extern "C" void kernel_launch(void* const* d_in, const int* in_sizes, int n_in,
                              void* d_out, int out_size)
{
    const float* hidden = (const float*)d_in[0];   // [8,128,768]
    const float* R      = (const float*)d_in[1];   // [1,8192,8192]
    const float* mask   = (const float*)d_in[2];   // [8,1,12,12]
    const float* Wq     = (const float*)d_in[3];
    const float* Wk     = (const float*)d_in[4];
    const float* Wv     = (const float*)d_in[5];
    const float* Wo     = (const float*)d_in[6];
    float* out = (float*)d_out;

    const int OUT_ELEMS  = B_ * S_ * E_;            // 786432
    const int ATTN_ELEMS = B_ * S_ * H_ * H_;       // 147456
    const int write_attn = (out_size >= OUT_ELEMS + ATTN_ELEMS) ? 1 : 0;

    // 1) fused QKV projections (q,k scattered into rotated layout)
    proj_kernel<<<dim3(E_ / BN, BSROWS / BM, 3), 256>>>(hidden, Wq, Wk, Wv);

    // 2) rotation GEMM: [192, 8192] @ R  (q and k share one pass over R)
    rot_kernel<<<dim3(SD_ / BN, QKROWS / BM), 256>>>(R);

    // 3) per-position head-axis attention (+ optional attn weights output)
    attn_kernel<<<BSROWS, ATTN_THREADS>>>(mask, out + OUT_ELEMS, write_attn);

    // 4) output projection -> d_out
    final_kernel<<<dim3(E_ / BN, BSROWS / BM), 256>>>(Wo, out);
}

// round 9
// speedup vs baseline: 2.0378x; 2.0378x over previous
#include <cuda_runtime.h>
#include <cuda_bf16.h>
#include <mma.h>
#include <cstdint>

using namespace nvcuda;

// Problem constants
#define B_  8
#define S_  128
#define E_  768
#define H_  12
#define D_  64
#define SD_ 8192          // S*D
#define BSROWS 1024       // B*S
#define QKROWS 192        // 2*B*H  (q rows 0..95, k rows 96..191)
#define AROWS  256        // padded M for rotation (rows 192..255 unused)

// SIMT GEMM tiling (proj / final)
#define BM 64
#define BN 128
#define BK 16
#define TM 4
#define TN 8

// ---------------- device scratch (static allocations only) ----------------
__device__ __nv_bfloat16 g_qa_hi[AROWS * SD_];  // A operand hi  [256, 8192] bf16 (4 MB)
__device__ __nv_bfloat16 g_qa_lo[AROWS * SD_];  // A operand lo                   (4 MB)
__device__ float g_qkr[QKROWS * SD_];           // rotated q/k fp32 [192, 8192]   (6 MB)
__device__ float g_v  [BSROWS * E_];            // v proj [1024, 768]             (3 MB)
__device__ float g_ctx[BSROWS * E_];            // ctx [B][H][S][D] == [1024,768] (3 MB)

// ==================== WMMA rotation kernel (baseline-ISA tensor path) ====================
// D[192(+pad), 8192] = A[256, 8192] @ R[8192, 8192]
// bf16 2-term split, 3 mma passes, fp32 accum. CTA tile 128x128, BK=32.
// grid (64 n-tiles, 2 m-tiles), 256 threads = 8 warps, warp tile 64(M) x 32(N).
#define BKR   32
#define NCHUNKS (SD_ / BKR)   // 256
#define A_LDM 40              // 128 rows x (32+8) bf16 ; 80B rows (16B mult, conflict-free)
#define B_LDM 136             // 32 rows x (128+8) bf16 ; 272B rows (16B mult, conflict-free)

__global__ void __launch_bounds__(256, 1)
rot_wmma_kernel(const float* __restrict__ R)
{
    __shared__ __nv_bfloat16 sAh[128 * A_LDM];
    __shared__ __nv_bfloat16 sAl[128 * A_LDM];
    __shared__ __nv_bfloat16 sBh[BKR * B_LDM];
    __shared__ __nv_bfloat16 sBl[BKR * B_LDM];

    const int tid = threadIdx.x;
    const int wid = tid >> 5;
    const int wm  = wid >> 2;       // 0..1  -> warp M offset wm*64
    const int wn  = wid & 3;        // 0..3  -> warp N offset wn*32
    const int n0  = blockIdx.x * 128;
    const int m0  = blockIdx.y * 128;

    wmma::fragment<wmma::accumulator, 16, 16, 16, float> acc[4][2];
    #pragma unroll
    for (int i = 0; i < 4; i++)
        #pragma unroll
        for (int j = 0; j < 2; j++) wmma::fill_fragment(acc[i][j], 0.0f);

    const __nv_bfloat16* gAh = g_qa_hi + (size_t)m0 * SD_;
    const __nv_bfloat16* gAl = g_qa_lo + (size_t)m0 * SD_;

    for (int c = 0; c < NCHUNKS; ++c) {
        const int k0 = c * BKR;

        // ---- load A tiles: [128 rows x 32 bf16], float4 (8 bf16) per op ----
        #pragma unroll
        for (int i = tid; i < 512; i += 256) {
            const int r  = i >> 2;
            const int c8 = (i & 3) << 3;
            *(float4*)&sAh[r * A_LDM + c8] = *(const float4*)(gAh + (size_t)r * SD_ + k0 + c8);
            *(float4*)&sAl[r * A_LDM + c8] = *(const float4*)(gAl + (size_t)r * SD_ + k0 + c8);
        }
        // ---- load+convert B tile: R[k0+kk][n0+n], fp32 -> bf16 hi/lo, stored [kk][n] ----
        #pragma unroll
        for (int i = tid; i < 1024; i += 256) {
            const int kk = i >> 5;
            const int n4 = (i & 31) << 2;
            const float4 rv = *(const float4*)(R + (size_t)(k0 + kk) * SD_ + n0 + n4);
            const float xs[4] = {rv.x, rv.y, rv.z, rv.w};
            __nv_bfloat16 h[4], l[4];
            #pragma unroll
            for (int j = 0; j < 4; j++) {
                h[j] = __float2bfloat16(xs[j]);
                l[j] = __float2bfloat16(xs[j] - __bfloat162float(h[j]));
            }
            *(__nv_bfloat162*)&sBh[kk * B_LDM + n4]     = __halves2bfloat162(h[0], h[1]);
            *(__nv_bfloat162*)&sBh[kk * B_LDM + n4 + 2] = __halves2bfloat162(h[2], h[3]);
            *(__nv_bfloat162*)&sBl[kk * B_LDM + n4]     = __halves2bfloat162(l[0], l[1]);
            *(__nv_bfloat162*)&sBl[kk * B_LDM + n4 + 2] = __halves2bfloat162(l[2], l[3]);
        }
        __syncthreads();

        // ---- compute: 2 k-steps of 16, 3 passes ----
        #pragma unroll
        for (int ks = 0; ks < 2; ks++) {
            wmma::fragment<wmma::matrix_a, 16, 16, 16, __nv_bfloat16, wmma::row_major> ah[4], al[4];
            wmma::fragment<wmma::matrix_b, 16, 16, 16, __nv_bfloat16, wmma::row_major> bh[2], bl[2];
            #pragma unroll
            for (int i = 0; i < 4; i++) {
                const __nv_bfloat16* pa = &sAh[(wm * 64 + i * 16) * A_LDM + ks * 16];
                const __nv_bfloat16* pl = &sAl[(wm * 64 + i * 16) * A_LDM + ks * 16];
                wmma::load_matrix_sync(ah[i], pa, A_LDM);
                wmma::load_matrix_sync(al[i], pl, A_LDM);
            }
            #pragma unroll
            for (int j = 0; j < 2; j++) {
                const __nv_bfloat16* pb = &sBh[(ks * 16) * B_LDM + wn * 32 + j * 16];
                const __nv_bfloat16* pq = &sBl[(ks * 16) * B_LDM + wn * 32 + j * 16];
                wmma::load_matrix_sync(bh[j], pb, B_LDM);
                wmma::load_matrix_sync(bl[j], pq, B_LDM);
            }
            #pragma unroll
            for (int i = 0; i < 4; i++)
                #pragma unroll
                for (int j = 0; j < 2; j++) {
                    wmma::mma_sync(acc[i][j], ah[i], bh[j], acc[i][j]);
                    wmma::mma_sync(acc[i][j], ah[i], bl[j], acc[i][j]);
                    wmma::mma_sync(acc[i][j], al[i], bh[j], acc[i][j]);
                }
        }
        __syncthreads();
    }

    // ---- store (skip pad rows >= 192; warp-tile granularity aligns with the 192 boundary) ----
    const int mrow = m0 + wm * 64;
    if (mrow < QKROWS) {
        #pragma unroll
        for (int i = 0; i < 4; i++)
            #pragma unroll
            for (int j = 0; j < 2; j++)
                wmma::store_matrix_sync(
                    g_qkr + (size_t)(mrow + i * 16) * SD_ + n0 + wn * 32 + j * 16,
                    acc[i][j], SD_, wmma::mem_row_major);
    }
}

// ==================== fp32 SIMT SGEMM (proj / final) ====================
// C[M,N] = A[M,K] * op(B).  TRANSB=true: B is [N,K] row-major (X @ W^T).
// epi=0: row-major fp32 store. epi=1: bf16 hi/lo split-scatter into g_qa_* rotated layout.
template<bool TRANSB>
__device__ __forceinline__ void sgemm_core(
    const float* __restrict__ A, const float* __restrict__ B, float* __restrict__ C,
    int N, int K, int epi, int scatter_base)
{
    __shared__ float As[2][BK][BM];
    __shared__ float Bs[2][BK][BN];

    const int tid = threadIdx.x;
    const int tx  = tid & 15;
    const int ty  = tid >> 4;
    const size_t bm = (size_t)blockIdx.y * BM;
    const size_t bn = (size_t)blockIdx.x * BN;

    const int arow = tid >> 2;
    const int acol = (tid & 3) << 2;
    const float* Ap = A + (bm + arow) * (size_t)K + acol;

    int br0, bc0, br1, bc1;
    const float *Bp0, *Bp1;
    if (!TRANSB) {
        const int f0 = tid * 2, f1 = f0 + 1;
        br0 = f0 >> 5; bc0 = (f0 & 31) << 2;
        br1 = f1 >> 5; bc1 = (f1 & 31) << 2;
        Bp0 = B + (size_t)br0 * N + bn + bc0;
        Bp1 = B + (size_t)br1 * N + bn + bc1;
    } else {
        const int f0 = tid * 2, f1 = f0 + 1;
        br0 = f0 >> 2; bc0 = (f0 & 3) << 2;
        br1 = f1 >> 2; bc1 = (f1 & 3) << 2;
        Bp0 = B + (bn + br0) * (size_t)K + bc0;
        Bp1 = B + (bn + br1) * (size_t)K + bc1;
    }

    float acc[TM][TN];
    #pragma unroll
    for (int i = 0; i < TM; i++)
        #pragma unroll
        for (int j = 0; j < TN; j++) acc[i][j] = 0.0f;

    {
        const float4 ra  = *(const float4*)Ap;
        const float4 rb0 = *(const float4*)Bp0;
        const float4 rb1 = *(const float4*)Bp1;
        As[0][acol + 0][arow] = ra.x; As[0][acol + 1][arow] = ra.y;
        As[0][acol + 2][arow] = ra.z; As[0][acol + 3][arow] = ra.w;
        if (!TRANSB) {
            *(float4*)&Bs[0][br0][bc0] = rb0;
            *(float4*)&Bs[0][br1][bc1] = rb1;
        } else {
            Bs[0][bc0 + 0][br0] = rb0.x; Bs[0][bc0 + 1][br0] = rb0.y;
            Bs[0][bc0 + 2][br0] = rb0.z; Bs[0][bc0 + 3][br0] = rb0.w;
            Bs[0][bc1 + 0][br1] = rb1.x; Bs[0][bc1 + 1][br1] = rb1.y;
            Bs[0][bc1 + 2][br1] = rb1.z; Bs[0][bc1 + 3][br1] = rb1.w;
        }
    }
    __syncthreads();

    const int nt = K / BK;
    for (int t = 0; t < nt; ++t) {
        const int buf = t & 1;
        float4 ra, rb0, rb1;
        const bool hasNext = (t + 1 < nt);
        if (hasNext) {
            const size_t koff = (size_t)(t + 1) * BK;
            ra = *(const float4*)(Ap + koff);
            if (!TRANSB) {
                rb0 = *(const float4*)(Bp0 + koff * N);
                rb1 = *(const float4*)(Bp1 + koff * N);
            } else {
                rb0 = *(const float4*)(Bp0 + koff);
                rb1 = *(const float4*)(Bp1 + koff);
            }
        }

        #pragma unroll
        for (int kk = 0; kk < BK; ++kk) {
            const float4 av  = *(const float4*)&As[buf][kk][ty * TM];
            const float4 bv0 = *(const float4*)&Bs[buf][kk][tx * TN];
            const float4 bv1 = *(const float4*)&Bs[buf][kk][tx * TN + 4];
            const float a[TM]  = {av.x, av.y, av.z, av.w};
            const float bb[TN] = {bv0.x, bv0.y, bv0.z, bv0.w,
                                  bv1.x, bv1.y, bv1.z, bv1.w};
            #pragma unroll
            for (int i = 0; i < TM; i++)
                #pragma unroll
                for (int j = 0; j < TN; j++)
                    acc[i][j] = fmaf(a[i], bb[j], acc[i][j]);
        }

        if (hasNext) {
            const int nb = buf ^ 1;
            As[nb][acol + 0][arow] = ra.x; As[nb][acol + 1][arow] = ra.y;
            As[nb][acol + 2][arow] = ra.z; As[nb][acol + 3][arow] = ra.w;
            if (!TRANSB) {
                *(float4*)&Bs[nb][br0][bc0] = rb0;
                *(float4*)&Bs[nb][br1][bc1] = rb1;
            } else {
                Bs[nb][bc0 + 0][br0] = rb0.x; Bs[nb][bc0 + 1][br0] = rb0.y;
                Bs[nb][bc0 + 2][br0] = rb0.z; Bs[nb][bc0 + 3][br0] = rb0.w;
                Bs[nb][bc1 + 0][br1] = rb1.x; Bs[nb][bc1 + 1][br1] = rb1.y;
                Bs[nb][bc1 + 2][br1] = rb1.z; Bs[nb][bc1 + 3][br1] = rb1.w;
            }
        }
        __syncthreads();
    }

    if (epi == 0) {
        #pragma unroll
        for (int i = 0; i < TM; i++) {
            float* cp = C + (bm + ty * TM + i) * (size_t)N + bn + tx * TN;
            *(float4*)(cp)     = make_float4(acc[i][0], acc[i][1], acc[i][2], acc[i][3]);
            *(float4*)(cp + 4) = make_float4(acc[i][4], acc[i][5], acc[i][6], acc[i][7]);
        }
    } else {
        // bf16 hi/lo split-scatter into rotation A layout
        #pragma unroll
        for (int i = 0; i < TM; i++) {
            const int r   = (int)bm + ty * TM + i;      // 0..1023
            const int bb_ = r >> 7;
            const int s   = r & 127;
            const int m   = (int)bn + tx * TN;          // multiple of 8, within one head
            const int h   = m >> 6;
            const int d   = m & 63;
            const size_t arow_g = (size_t)(scatter_base + bb_ * H_ + h);
            __nv_bfloat16* ph = g_qa_hi + (arow_g << 13) + s * D_ + d;
            __nv_bfloat16* pl = g_qa_lo + (arow_g << 13) + s * D_ + d;
            #pragma unroll
            for (int j = 0; j < TN; j++) {
                const float x = acc[i][j];
                const __nv_bfloat16 hh = __float2bfloat16(x);
                ph[j] = hh;
                pl[j] = __float2bfloat16(x - __bfloat162float(hh));
            }
        }
    }
}

// Fused QKV projection: grid (6, 16, 3)
__global__ __launch_bounds__(256, 2)
void proj_kernel(const float* __restrict__ X,
                 const float* __restrict__ Wq,
                 const float* __restrict__ Wk,
                 const float* __restrict__ Wv)
{
    const float* W;
    float* Cc;
    int epi, base;
    if (blockIdx.z == 0)      { W = Wq; Cc = nullptr; epi = 1; base = 0;  }
    else if (blockIdx.z == 1) { W = Wk; Cc = nullptr; epi = 1; base = 96; }
    else                      { W = Wv; Cc = g_v;     epi = 0; base = 0;  }
    sgemm_core<true>(X, W, Cc, E_, E_, epi, base);
}

// Output projection: ctx[1024,768] @ Wo^T ; grid (6, 16)
__global__ __launch_bounds__(256, 2)
void final_kernel(const float* __restrict__ Wo, float* __restrict__ out)
{
    sgemm_core<true>(g_ctx, Wo, out, E_, E_, 0, 0);
}

// Per-(b,s) head-axis attention. grid 1024, block 192 (>= H*H = 144).
#define ATTN_THREADS 192
__global__ __launch_bounds__(ATTN_THREADS)
void attn_kernel(const float* __restrict__ mask,
                 float* __restrict__ attn_out,
                 int write_attn)
{
    const int bs = blockIdx.x;
    const int b  = bs >> 7;
    const int s  = bs & 127;
    const int tid = threadIdx.x;

    __shared__ float qs[H_ * D_];
    __shared__ float ks[H_ * D_];
    __shared__ float vs[H_ * D_];
    __shared__ float aw[H_ * H_];

    for (int i = tid; i < H_ * D_; i += ATTN_THREADS) {
        const int h = i >> 6, d = i & 63;
        qs[i] = g_qkr[(((size_t)(b * H_ + h)) << 13) + s * D_ + d];
        ks[i] = g_qkr[(((size_t)(96 + b * H_ + h)) << 13) + s * D_ + d];
        vs[i] = g_v[(size_t)bs * E_ + i];
    }
    __syncthreads();

    if (tid < H_ * H_) {
        const int h = tid / H_, g = tid % H_;
        float acc = 0.0f;
        #pragma unroll
        for (int d = 0; d < D_; d++) acc += qs[h * D_ + d] * ks[g * D_ + d];
        aw[tid] = acc * 0.125f + mask[b * (H_ * H_) + tid];
    }
    __syncthreads();

    if (tid < H_) {
        float mx = -3.0e38f;
        #pragma unroll
        for (int g = 0; g < H_; g++) mx = fmaxf(mx, aw[tid * H_ + g]);
        float e[H_];
        float sum = 0.0f;
        #pragma unroll
        for (int g = 0; g < H_; g++) { e[g] = expf(aw[tid * H_ + g] - mx); sum += e[g]; }
        const float inv = 1.0f / sum;
        #pragma unroll
        for (int g = 0; g < H_; g++) aw[tid * H_ + g] = e[g] * inv;
    }
    __syncthreads();

    if (write_attn && tid < H_ * H_)
        attn_out[(size_t)bs * (H_ * H_) + tid] = aw[tid];

    for (int i = tid; i < H_ * D_; i += ATTN_THREADS) {
        const int h = i >> 6, d = i & 63;
        float acc = 0.0f;
        #pragma unroll
        for (int g = 0; g < H_; g++) acc += aw[h * H_ + g] * vs[g * D_ + d];
        g_ctx[(size_t)b * (H_ * S_ * D_) + h * (S_ * D_) + s * D_ + d] = acc;
    }
}

// ---------------- launch ----------------
extern "C" void kernel_launch(void* const* d_in, const int* in_sizes, int n_in,
                              void* d_out, int out_size)
{
    const float* hidden = (const float*)d_in[0];
    const float* R      = (const float*)d_in[1];
    const float* mask   = (const float*)d_in[2];
    const float* Wq     = (const float*)d_in[3];
    const float* Wk     = (const float*)d_in[4];
    const float* Wv     = (const float*)d_in[5];
    const float* Wo     = (const float*)d_in[6];
    float* out = (float*)d_out;

    const int OUT_ELEMS  = B_ * S_ * E_;
    const int ATTN_ELEMS = B_ * S_ * H_ * H_;
    const int write_attn = (out_size >= OUT_ELEMS + ATTN_ELEMS) ? 1 : 0;

    // 1) fused QKV projections (q,k emitted as bf16 hi/lo in rotated layout)
    proj_kernel<<<dim3(E_ / BN, BSROWS / BM, 3), 256>>>(hidden, Wq, Wk, Wv);

    // 2) rotation on WMMA tensor path: bf16 split 3-pass, fp32 accumulate
    rot_wmma_kernel<<<dim3(SD_ / 128, 2), 256>>>(R);

    // 3) per-position head-axis attention
    attn_kernel<<<BSROWS, ATTN_THREADS>>>(mask, out + OUT_ELEMS, write_attn);

    // 4) output projection -> d_out
    final_kernel<<<dim3(E_ / BN, BSROWS / BM), 256>>>(Wo, out);
}

// round 12
// speedup vs baseline: 2.7849x; 1.3666x over previous
#include <cuda_runtime.h>
#include <cuda_bf16.h>
#include <mma.h>
#include <cstdint>

using namespace nvcuda;

// Problem constants
#define B_  8
#define S_  128
#define E_  768
#define H_  12
#define D_  64
#define SD_ 8192          // S*D
#define BSROWS 1024       // B*S
#define QKROWS 192        // 2*B*H  (q rows 0..95, k rows 96..191)

// ---------------- device scratch (static allocations only) ----------------
__device__ __nv_bfloat16 g_qa_hi[QKROWS * SD_];  // A operand hi [192, 8192] bf16 (3 MB)
__device__ __nv_bfloat16 g_qa_lo[QKROWS * SD_];  // A operand lo                  (3 MB)
__device__ float g_qkr[QKROWS * SD_];            // rotated q/k fp32 [192, 8192]  (6 MB)
__device__ float g_v  [BSROWS * E_];             // v proj [1024, 768]            (3 MB)
__device__ float g_ctx[BSROWS * E_];             // ctx [B][H][S][D] == [1024,768](3 MB)

// split a float into bf16 hi + bf16 lo (hi = rn(x), lo = rn(x - hi))
__device__ __forceinline__ void bsplit(float x, __nv_bfloat16& h, __nv_bfloat16& l) {
    h = __float2bfloat16(x);
    l = __float2bfloat16(x - __bfloat162float(h));
}
__device__ __forceinline__ void split4_store(__nv_bfloat16* ph, __nv_bfloat16* pl, float4 v) {
    __nv_bfloat16 h[4], l[4];
    bsplit(v.x, h[0], l[0]); bsplit(v.y, h[1], l[1]);
    bsplit(v.z, h[2], l[2]); bsplit(v.w, h[3], l[3]);
    *(__nv_bfloat162*)(ph)     = __halves2bfloat162(h[0], h[1]);
    *(__nv_bfloat162*)(ph + 2) = __halves2bfloat162(h[2], h[3]);
    *(__nv_bfloat162*)(pl)     = __halves2bfloat162(l[0], l[1]);
    *(__nv_bfloat162*)(pl + 2) = __halves2bfloat162(l[2], l[3]);
}

// ==================== WMMA split GEMM, K=768 (QKV projection) ====================
// C[m][n] = sum_k A[m][k] * W[n][k].  A fp32 [1024,768], W fp32 [768,768] row-major.
// CTA tile 128x128, BK=32, 8 warps (2m x 4n), warp tile 64x32, 3-pass bf16 split.
// z=2 (V): fp32 row-major store into g_v.
// z=0/1 (Q/K): bf16 hi/lo split-scatter into g_qa_* rotated layout.
__global__ void __launch_bounds__(256, 1)
wproj_kernel(const float* __restrict__ X,
             const float* __restrict__ Wq,
             const float* __restrict__ Wk,
             const float* __restrict__ Wv)
{
    __shared__ __nv_bfloat16 sAh[128 * 40], sAl[128 * 40];
    __shared__ __nv_bfloat16 sBh[128 * 40], sBl[128 * 40];

    const float* W; int epi, base;
    if (blockIdx.z == 0)      { W = Wq; epi = 1; base = 0;  }
    else if (blockIdx.z == 1) { W = Wk; epi = 1; base = 96; }
    else                      { W = Wv; epi = 0; base = 0;  }

    const int tid  = threadIdx.x;
    const int wid  = tid >> 5;
    const int lane = tid & 31;
    const int wm   = wid >> 2;      // 0..1
    const int wn   = wid & 3;       // 0..3
    const int bm   = blockIdx.y * 128;
    const int bn   = blockIdx.x * 128;

    wmma::fragment<wmma::accumulator, 16, 16, 16, float> acc[4][2];
    #pragma unroll
    for (int i = 0; i < 4; i++)
        #pragma unroll
        for (int j = 0; j < 2; j++) wmma::fill_fragment(acc[i][j], 0.0f);

    float4 ra[4], rb[4];
    // prefetch chunk t into registers
    auto ldrs = [&](int t) {
        const int k0 = t * 32;
        #pragma unroll
        for (int u = 0; u < 4; u++) {
            const int i = tid + u * 256;           // 0..1023
            const int r = i >> 3, c = (i & 7) << 2;
            ra[u] = *(const float4*)(X + (size_t)(bm + r) * E_ + k0 + c);
            rb[u] = *(const float4*)(W + (size_t)(bn + r) * E_ + k0 + c);
        }
    };
    auto store_smem = [&]() {
        #pragma unroll
        for (int u = 0; u < 4; u++) {
            const int i = tid + u * 256;
            const int r = i >> 3, c = (i & 7) << 2;
            split4_store(&sAh[r * 40 + c], &sAl[r * 40 + c], ra[u]);
            split4_store(&sBh[r * 40 + c], &sBl[r * 40 + c], rb[u]);
        }
    };

    ldrs(0);
    for (int t = 0; t < 24; ++t) {
        store_smem();
        __syncthreads();
        if (t + 1 < 24) ldrs(t + 1);

        #pragma unroll
        for (int ks = 0; ks < 2; ks++) {
            wmma::fragment<wmma::matrix_a, 16, 16, 16, __nv_bfloat16, wmma::row_major> ah[4], al[4];
            wmma::fragment<wmma::matrix_b, 16, 16, 16, __nv_bfloat16, wmma::col_major> bh[2], bl[2];
            #pragma unroll
            for (int i = 0; i < 4; i++) {
                wmma::load_matrix_sync(ah[i], &sAh[(wm * 64 + i * 16) * 40 + ks * 16], 40);
                wmma::load_matrix_sync(al[i], &sAl[(wm * 64 + i * 16) * 40 + ks * 16], 40);
            }
            #pragma unroll
            for (int j = 0; j < 2; j++) {
                wmma::load_matrix_sync(bh[j], &sBh[(wn * 32 + j * 16) * 40 + ks * 16], 40);
                wmma::load_matrix_sync(bl[j], &sBl[(wn * 32 + j * 16) * 40 + ks * 16], 40);
            }
            #pragma unroll
            for (int i = 0; i < 4; i++)
                #pragma unroll
                for (int j = 0; j < 2; j++) {
                    wmma::mma_sync(acc[i][j], ah[i], bh[j], acc[i][j]);
                    wmma::mma_sync(acc[i][j], ah[i], bl[j], acc[i][j]);
                    wmma::mma_sync(acc[i][j], al[i], bh[j], acc[i][j]);
                }
        }
        __syncthreads();
    }

    // ---- epilogue ----
    if (epi == 0) {
        #pragma unroll
        for (int i = 0; i < 4; i++)
            #pragma unroll
            for (int j = 0; j < 2; j++)
                wmma::store_matrix_sync(
                    g_v + (size_t)(bm + wm * 64 + i * 16) * E_ + bn + wn * 32 + j * 16,
                    acc[i][j], E_, wmma::mem_row_major);
    } else {
        // reuse dead sAh as fp32 staging (128*40 bf16 = 10240B >= 8*256*4B = 8192B needed)
        float* stage = (float*)sAh;
        float* my = stage + wid * 256;
        #pragma unroll
        for (int i = 0; i < 4; i++)
            #pragma unroll
            for (int j = 0; j < 2; j++) {
                wmma::store_matrix_sync(my, acc[i][j], 16, wmma::mem_row_major);
                __syncwarp();
                const int rr = lane >> 1, hc = lane & 1;
                const float* src = my + rr * 16 + hc * 8;
                const int gr = bm + wm * 64 + i * 16 + rr;      // 0..1023
                const int gc = bn + wn * 32 + j * 16 + hc * 8;  // multiple of 8, one head
                const int b = gr >> 7, s = gr & 127;
                const int h = gc >> 6, d = gc & 63;
                const size_t off = ((size_t)(base + b * H_ + h) << 13) + s * D_ + d;
                union { __nv_bfloat162 b2[4]; uint4 u; } uh, ul;
                #pragma unroll
                for (int p = 0; p < 4; p++) {
                    __nv_bfloat16 h0, l0, h1, l1;
                    bsplit(src[p * 2 + 0], h0, l0);
                    bsplit(src[p * 2 + 1], h1, l1);
                    uh.b2[p] = __halves2bfloat162(h0, h1);
                    ul.b2[p] = __halves2bfloat162(l0, l1);
                }
                *(uint4*)(g_qa_hi + off) = uh.u;
                *(uint4*)(g_qa_lo + off) = ul.u;
                __syncwarp();
            }
    }
}

// final: out = ctx @ Wo^T (same core), grid (6,8)
__global__ void __launch_bounds__(256, 1)
wfinal_kernel(const float* __restrict__ Wo, float* __restrict__ out)
{
    __shared__ __nv_bfloat16 sAh[128 * 40], sAl[128 * 40];
    __shared__ __nv_bfloat16 sBh[128 * 40], sBl[128 * 40];

    const int tid = threadIdx.x;
    const int wid = tid >> 5;
    const int wm  = wid >> 2;
    const int wn  = wid & 3;
    const int bm  = blockIdx.y * 128;
    const int bn  = blockIdx.x * 128;

    wmma::fragment<wmma::accumulator, 16, 16, 16, float> acc[4][2];
    #pragma unroll
    for (int i = 0; i < 4; i++)
        #pragma unroll
        for (int j = 0; j < 2; j++) wmma::fill_fragment(acc[i][j], 0.0f);

    float4 ra[4], rb[4];
    auto ldrs = [&](int t) {
        const int k0 = t * 32;
        #pragma unroll
        for (int u = 0; u < 4; u++) {
            const int i = tid + u * 256;
            const int r = i >> 3, c = (i & 7) << 2;
            ra[u] = *(const float4*)(g_ctx + (size_t)(bm + r) * E_ + k0 + c);
            rb[u] = *(const float4*)(Wo + (size_t)(bn + r) * E_ + k0 + c);
        }
    };
    auto store_smem = [&]() {
        #pragma unroll
        for (int u = 0; u < 4; u++) {
            const int i = tid + u * 256;
            const int r = i >> 3, c = (i & 7) << 2;
            split4_store(&sAh[r * 40 + c], &sAl[r * 40 + c], ra[u]);
            split4_store(&sBh[r * 40 + c], &sBl[r * 40 + c], rb[u]);
        }
    };

    ldrs(0);
    for (int t = 0; t < 24; ++t) {
        store_smem();
        __syncthreads();
        if (t + 1 < 24) ldrs(t + 1);
        #pragma unroll
        for (int ks = 0; ks < 2; ks++) {
            wmma::fragment<wmma::matrix_a, 16, 16, 16, __nv_bfloat16, wmma::row_major> ah[4], al[4];
            wmma::fragment<wmma::matrix_b, 16, 16, 16, __nv_bfloat16, wmma::col_major> bh[2], bl[2];
            #pragma unroll
            for (int i = 0; i < 4; i++) {
                wmma::load_matrix_sync(ah[i], &sAh[(wm * 64 + i * 16) * 40 + ks * 16], 40);
                wmma::load_matrix_sync(al[i], &sAl[(wm * 64 + i * 16) * 40 + ks * 16], 40);
            }
            #pragma unroll
            for (int j = 0; j < 2; j++) {
                wmma::load_matrix_sync(bh[j], &sBh[(wn * 32 + j * 16) * 40 + ks * 16], 40);
                wmma::load_matrix_sync(bl[j], &sBl[(wn * 32 + j * 16) * 40 + ks * 16], 40);
            }
            #pragma unroll
            for (int i = 0; i < 4; i++)
                #pragma unroll
                for (int j = 0; j < 2; j++) {
                    wmma::mma_sync(acc[i][j], ah[i], bh[j], acc[i][j]);
                    wmma::mma_sync(acc[i][j], ah[i], bl[j], acc[i][j]);
                    wmma::mma_sync(acc[i][j], al[i], bh[j], acc[i][j]);
                }
        }
        __syncthreads();
    }

    #pragma unroll
    for (int i = 0; i < 4; i++)
        #pragma unroll
        for (int j = 0; j < 2; j++)
            wmma::store_matrix_sync(
                out + (size_t)(bm + wm * 64 + i * 16) * E_ + bn + wn * 32 + j * 16,
                acc[i][j], E_, wmma::mem_row_major);
}

// ==================== WMMA rotation kernel ====================
// D[192, 8192] = A[192, 8192] @ R[8192, 8192]
// grid (64 n-tiles, 2 m-tiles of 96), 256 threads = 8 warps (2m x 4n), warp tile 48x32.
// A pre-split bf16 hi/lo (from proj); R converted fp32->hi/lo on the fly.
// Register-prefetch pipeline: loads for chunk t+1 issue before MMAs of chunk t.
#define RBK 32
#define RNCH (SD_ / RBK)      // 256 chunks
#define RA_LDM 40
#define RB_LDM 136

__global__ void __launch_bounds__(256, 1)
rot_wmma_kernel(const float* __restrict__ R)
{
    __shared__ __nv_bfloat16 sAh[96 * RA_LDM], sAl[96 * RA_LDM];
    __shared__ __nv_bfloat16 sBh[RBK * RB_LDM], sBl[RBK * RB_LDM];

    const int tid = threadIdx.x;
    const int wid = tid >> 5;
    const int wm  = wid >> 2;       // 0..1 -> m offset wm*48
    const int wn  = wid & 3;        // 0..3 -> n offset wn*32
    const int n0  = blockIdx.x * 128;
    const int m0  = blockIdx.y * 96;

    wmma::fragment<wmma::accumulator, 16, 16, 16, float> acc[3][2];
    #pragma unroll
    for (int i = 0; i < 3; i++)
        #pragma unroll
        for (int j = 0; j < 2; j++) wmma::fill_fragment(acc[i][j], 0.0f);

    uint2 pah[3], pal[3];
    float4 prb[4];
    auto ldrs = [&](int t) {
        const int k0 = t * RBK;
        #pragma unroll
        for (int u = 0; u < 3; u++) {
            const int i = tid + u * 256;          // 0..767 : 96 rows x 8 uint2
            const int r = i >> 3, c = (i & 7) << 2;
            pah[u] = *(const uint2*)(g_qa_hi + (size_t)(m0 + r) * SD_ + k0 + c);
            pal[u] = *(const uint2*)(g_qa_lo + (size_t)(m0 + r) * SD_ + k0 + c);
        }
        #pragma unroll
        for (int u = 0; u < 4; u++) {
            const int i = tid + u * 256;          // 0..1023 : 32 k-rows x 32 float4
            const int kk = i >> 5, n4 = (i & 31) << 2;
            prb[u] = *(const float4*)(R + (size_t)(k0 + kk) * SD_ + n0 + n4);
        }
    };
    auto store_smem = [&]() {
        #pragma unroll
        for (int u = 0; u < 3; u++) {
            const int i = tid + u * 256;
            const int r = i >> 3, c = (i & 7) << 2;
            *(uint2*)&sAh[r * RA_LDM + c] = pah[u];
            *(uint2*)&sAl[r * RA_LDM + c] = pal[u];
        }
        #pragma unroll
        for (int u = 0; u < 4; u++) {
            const int i = tid + u * 256;
            const int kk = i >> 5, n4 = (i & 31) << 2;
            split4_store(&sBh[kk * RB_LDM + n4], &sBl[kk * RB_LDM + n4], prb[u]);
        }
    };

    ldrs(0);
    for (int t = 0; t < RNCH; ++t) {
        store_smem();
        __syncthreads();
        if (t + 1 < RNCH) ldrs(t + 1);

        #pragma unroll
        for (int ks = 0; ks < 2; ks++) {
            wmma::fragment<wmma::matrix_a, 16, 16, 16, __nv_bfloat16, wmma::row_major> ah[3], al[3];
            wmma::fragment<wmma::matrix_b, 16, 16, 16, __nv_bfloat16, wmma::row_major> bh[2], bl[2];
            #pragma unroll
            for (int i = 0; i < 3; i++) {
                wmma::load_matrix_sync(ah[i], &sAh[(wm * 48 + i * 16) * RA_LDM + ks * 16], RA_LDM);
                wmma::load_matrix_sync(al[i], &sAl[(wm * 48 + i * 16) * RA_LDM + ks * 16], RA_LDM);
            }
            #pragma unroll
            for (int j = 0; j < 2; j++) {
                wmma::load_matrix_sync(bh[j], &sBh[(ks * 16) * RB_LDM + wn * 32 + j * 16], RB_LDM);
                wmma::load_matrix_sync(bl[j], &sBl[(ks * 16) * RB_LDM + wn * 32 + j * 16], RB_LDM);
            }
            #pragma unroll
            for (int i = 0; i < 3; i++)
                #pragma unroll
                for (int j = 0; j < 2; j++) {
                    wmma::mma_sync(acc[i][j], ah[i], bh[j], acc[i][j]);
                    wmma::mma_sync(acc[i][j], ah[i], bl[j], acc[i][j]);
                    wmma::mma_sync(acc[i][j], al[i], bh[j], acc[i][j]);
                }
        }
        __syncthreads();
    }

    #pragma unroll
    for (int i = 0; i < 3; i++)
        #pragma unroll
        for (int j = 0; j < 2; j++)
            wmma::store_matrix_sync(
                g_qkr + (size_t)(m0 + wm * 48 + i * 16) * SD_ + n0 + wn * 32 + j * 16,
                acc[i][j], SD_, wmma::mem_row_major);
}

// ==================== per-(b,s) head-axis attention ====================
#define ATTN_THREADS 192
__global__ void __launch_bounds__(ATTN_THREADS)
attn_kernel(const float* __restrict__ mask,
            float* __restrict__ attn_out,
            int write_attn)
{
    const int bs = blockIdx.x;
    const int b  = bs >> 7;
    const int s  = bs & 127;
    const int tid = threadIdx.x;

    __shared__ float qs[H_ * D_];
    __shared__ float ks[H_ * D_];
    __shared__ float vs[H_ * D_];
    __shared__ float aw[H_ * H_];

    for (int i = tid; i < H_ * D_; i += ATTN_THREADS) {
        const int h = i >> 6, d = i & 63;
        qs[i] = g_qkr[(((size_t)(b * H_ + h)) << 13) + s * D_ + d];
        ks[i] = g_qkr[(((size_t)(96 + b * H_ + h)) << 13) + s * D_ + d];
        vs[i] = g_v[(size_t)bs * E_ + i];
    }
    __syncthreads();

    if (tid < H_ * H_) {
        const int h = tid / H_, g = tid % H_;
        float acc = 0.0f;
        #pragma unroll
        for (int d = 0; d < D_; d++) acc += qs[h * D_ + d] * ks[g * D_ + d];
        aw[tid] = acc * 0.125f + mask[b * (H_ * H_) + tid];
    }
    __syncthreads();

    if (tid < H_) {
        float mx = -3.0e38f;
        #pragma unroll
        for (int g = 0; g < H_; g++) mx = fmaxf(mx, aw[tid * H_ + g]);
        float e[H_];
        float sum = 0.0f;
        #pragma unroll
        for (int g = 0; g < H_; g++) { e[g] = expf(aw[tid * H_ + g] - mx); sum += e[g]; }
        const float inv = 1.0f / sum;
        #pragma unroll
        for (int g = 0; g < H_; g++) aw[tid * H_ + g] = e[g] * inv;
    }
    __syncthreads();

    if (write_attn && tid < H_ * H_)
        attn_out[(size_t)bs * (H_ * H_) + tid] = aw[tid];

    for (int i = tid; i < H_ * D_; i += ATTN_THREADS) {
        const int h = i >> 6, d = i & 63;
        float acc = 0.0f;
        #pragma unroll
        for (int g = 0; g < H_; g++) acc += aw[h * H_ + g] * vs[g * D_ + d];
        g_ctx[(size_t)b * (H_ * S_ * D_) + h * (S_ * D_) + s * D_ + d] = acc;
    }
}

// ---------------- launch ----------------
extern "C" void kernel_launch(void* const* d_in, const int* in_sizes, int n_in,
                              void* d_out, int out_size)
{
    const float* hidden = (const float*)d_in[0];
    const float* R      = (const float*)d_in[1];
    const float* mask   = (const float*)d_in[2];
    const float* Wq     = (const float*)d_in[3];
    const float* Wk     = (const float*)d_in[4];
    const float* Wv     = (const float*)d_in[5];
    const float* Wo     = (const float*)d_in[6];
    float* out = (float*)d_out;

    const int OUT_ELEMS  = B_ * S_ * E_;
    const int ATTN_ELEMS = B_ * S_ * H_ * H_;
    const int write_attn = (out_size >= OUT_ELEMS + ATTN_ELEMS) ? 1 : 0;

    // 1) WMMA QKV projections (q,k emitted as bf16 hi/lo in rotated layout; v -> g_v)
    wproj_kernel<<<dim3(E_ / 128, BSROWS / 128, 3), 256>>>(hidden, Wq, Wk, Wv);

    // 2) WMMA rotation: bf16 split 3-pass, fp32 accumulate, register-prefetch pipeline
    rot_wmma_kernel<<<dim3(SD_ / 128, 2), 256>>>(R);

    // 3) per-position head-axis attention
    attn_kernel<<<BSROWS, ATTN_THREADS>>>(mask, out + OUT_ELEMS, write_attn);

    // 4) WMMA output projection -> d_out
    wfinal_kernel<<<dim3(E_ / 128, BSROWS / 128), 256>>>(Wo, out);
}

// round 13
// speedup vs baseline: 2.8714x; 1.0311x over previous
#include <cuda_runtime.h>
#include <cuda_bf16.h>
#include <mma.h>
#include <cstdint>

using namespace nvcuda;

// Problem constants
#define B_  8
#define S_  128
#define E_  768
#define H_  12
#define D_  64
#define SD_ 8192          // S*D
#define BSROWS 1024       // B*S
#define QKROWS 192        // 2*B*H  (q rows 0..95, k rows 96..191)

// ---------------- device scratch (static allocations only) ----------------
__device__ __nv_bfloat16 g_qa_hi[QKROWS * SD_];  // A operand hi [192, 8192] bf16 (3 MB)
__device__ __nv_bfloat16 g_qa_lo[QKROWS * SD_];  // A operand lo                  (3 MB)
__device__ float g_qkr[QKROWS * SD_];            // rotated q/k fp32 [192, 8192]  (6 MB)
__device__ float g_v  [BSROWS * E_];             // v proj [1024, 768]            (3 MB)
__device__ float g_ctx[BSROWS * E_];             // ctx [B][H][S][D] == [1024,768](3 MB)

// split a float into bf16 hi + bf16 lo (hi = rn(x), lo = rn(x - hi))
__device__ __forceinline__ void bsplit(float x, __nv_bfloat16& h, __nv_bfloat16& l) {
    h = __float2bfloat16(x);
    l = __float2bfloat16(x - __bfloat162float(h));
}
__device__ __forceinline__ void split4_store(__nv_bfloat16* ph, __nv_bfloat16* pl, float4 v) {
    __nv_bfloat16 h[4], l[4];
    bsplit(v.x, h[0], l[0]); bsplit(v.y, h[1], l[1]);
    bsplit(v.z, h[2], l[2]); bsplit(v.w, h[3], l[3]);
    *(__nv_bfloat162*)(ph)     = __halves2bfloat162(h[0], h[1]);
    *(__nv_bfloat162*)(ph + 2) = __halves2bfloat162(h[2], h[3]);
    *(__nv_bfloat162*)(pl)     = __halves2bfloat162(l[0], l[1]);
    *(__nv_bfloat162*)(pl + 2) = __halves2bfloat162(l[2], l[3]);
}

// ==================== WMMA split GEMM, K=768, CTA tile 64x64 (QKV proj) ====================
// C[m][n] = sum_k A[m][k] * W[n][k].  8 warps (2m x 4n), warp tile 32x16, 3-pass bf16 split.
// 20.5 KB smem, 2 CTAs/SM.  z=2 (V): fp32 store to g_v.  z=0/1 (Q/K): split-scatter to g_qa_*.
__global__ void __launch_bounds__(256, 2)
wproj_kernel(const float* __restrict__ X,
             const float* __restrict__ Wq,
             const float* __restrict__ Wk,
             const float* __restrict__ Wv)
{
    __shared__ __nv_bfloat16 sAh[64 * 40], sAl[64 * 40];
    __shared__ __nv_bfloat16 sBh[64 * 40], sBl[64 * 40];

    const float* W; int epi, base;
    if (blockIdx.z == 0)      { W = Wq; epi = 1; base = 0;  }
    else if (blockIdx.z == 1) { W = Wk; epi = 1; base = 96; }
    else                      { W = Wv; epi = 0; base = 0;  }

    const int tid  = threadIdx.x;
    const int wid  = tid >> 5;
    const int lane = tid & 31;
    const int wm   = wid >> 2;      // 0..1 -> m offset wm*32
    const int wn   = wid & 3;       // 0..3 -> n offset wn*16
    const int bm   = blockIdx.y * 64;
    const int bn   = blockIdx.x * 64;

    wmma::fragment<wmma::accumulator, 16, 16, 16, float> acc[2];
    #pragma unroll
    for (int i = 0; i < 2; i++) wmma::fill_fragment(acc[i], 0.0f);

    float4 ra[2], rb[2];
    auto ldrs = [&](int t) {
        const int k0 = t * 32;
        #pragma unroll
        for (int u = 0; u < 2; u++) {
            const int i = tid + u * 256;           // 0..511 : 64 rows x 8 float4
            const int r = i >> 3, c = (i & 7) << 2;
            ra[u] = *(const float4*)(X + (size_t)(bm + r) * E_ + k0 + c);
            rb[u] = *(const float4*)(W + (size_t)(bn + r) * E_ + k0 + c);
        }
    };
    auto store_smem = [&]() {
        #pragma unroll
        for (int u = 0; u < 2; u++) {
            const int i = tid + u * 256;
            const int r = i >> 3, c = (i & 7) << 2;
            split4_store(&sAh[r * 40 + c], &sAl[r * 40 + c], ra[u]);
            split4_store(&sBh[r * 40 + c], &sBl[r * 40 + c], rb[u]);
        }
    };

    ldrs(0);
    for (int t = 0; t < 24; ++t) {
        store_smem();
        __syncthreads();
        if (t + 1 < 24) ldrs(t + 1);

        #pragma unroll
        for (int ks = 0; ks < 2; ks++) {
            wmma::fragment<wmma::matrix_a, 16, 16, 16, __nv_bfloat16, wmma::row_major> ah[2], al[2];
            wmma::fragment<wmma::matrix_b, 16, 16, 16, __nv_bfloat16, wmma::col_major> bh, bl;
            #pragma unroll
            for (int i = 0; i < 2; i++) {
                wmma::load_matrix_sync(ah[i], &sAh[(wm * 32 + i * 16) * 40 + ks * 16], 40);
                wmma::load_matrix_sync(al[i], &sAl[(wm * 32 + i * 16) * 40 + ks * 16], 40);
            }
            wmma::load_matrix_sync(bh, &sBh[(wn * 16) * 40 + ks * 16], 40);
            wmma::load_matrix_sync(bl, &sBl[(wn * 16) * 40 + ks * 16], 40);
            #pragma unroll
            for (int i = 0; i < 2; i++) {
                wmma::mma_sync(acc[i], ah[i], bh, acc[i]);
                wmma::mma_sync(acc[i], ah[i], bl, acc[i]);
                wmma::mma_sync(acc[i], al[i], bh, acc[i]);
            }
        }
        __syncthreads();
    }

    // ---- epilogue ----
    if (epi == 0) {
        #pragma unroll
        for (int i = 0; i < 2; i++)
            wmma::store_matrix_sync(
                g_v + (size_t)(bm + wm * 32 + i * 16) * E_ + bn + wn * 16,
                acc[i], E_, wmma::mem_row_major);
    } else {
        // reuse dead sAh as fp32 staging (64*40 bf16 = 5120B < 8192B needed) -> use sAh+sAl (10240B)
        float* stage = (float*)sAh;              // sAh & sAl are contiguous? not guaranteed; use per-warp slice of sAh+sBh instead
        // 8 warps x 256 floats = 8192 B. sAh alone is 5120 B, so warps 0..4 use sAh, 5..7 use sBh.
        float* my = (wid < 4) ? ((float*)sAh + wid * 256)
                              : ((float*)sBh + (wid - 4) * 256);
        (void)stage;
        #pragma unroll
        for (int i = 0; i < 2; i++) {
            wmma::store_matrix_sync(my, acc[i], 16, wmma::mem_row_major);
            __syncwarp();
            const int rr = lane >> 1, hc = lane & 1;
            const float* src = my + rr * 16 + hc * 8;
            const int gr = bm + wm * 32 + i * 16 + rr;      // 0..1023
            const int gc = bn + wn * 16 + hc * 8;           // multiple of 8, one head
            const int b = gr >> 7, s = gr & 127;
            const int h = gc >> 6, d = gc & 63;
            const size_t off = ((size_t)(base + b * H_ + h) << 13) + s * D_ + d;
            union { __nv_bfloat162 b2[4]; uint4 u; } uh, ul;
            #pragma unroll
            for (int p = 0; p < 4; p++) {
                __nv_bfloat16 h0, l0, h1, l1;
                bsplit(src[p * 2 + 0], h0, l0);
                bsplit(src[p * 2 + 1], h1, l1);
                uh.b2[p] = __halves2bfloat162(h0, h1);
                ul.b2[p] = __halves2bfloat162(l0, l1);
            }
            *(uint4*)(g_qa_hi + off) = uh.u;
            *(uint4*)(g_qa_lo + off) = ul.u;
            __syncwarp();
        }
    }
}

// final: out = ctx @ Wo^T, CTA tile 64x64, grid (12,16)
__global__ void __launch_bounds__(256, 2)
wfinal_kernel(const float* __restrict__ Wo, float* __restrict__ out)
{
    __shared__ __nv_bfloat16 sAh[64 * 40], sAl[64 * 40];
    __shared__ __nv_bfloat16 sBh[64 * 40], sBl[64 * 40];

    const int tid = threadIdx.x;
    const int wid = tid >> 5;
    const int wm  = wid >> 2;
    const int wn  = wid & 3;
    const int bm  = blockIdx.y * 64;
    const int bn  = blockIdx.x * 64;

    wmma::fragment<wmma::accumulator, 16, 16, 16, float> acc[2];
    #pragma unroll
    for (int i = 0; i < 2; i++) wmma::fill_fragment(acc[i], 0.0f);

    float4 ra[2], rb[2];
    auto ldrs = [&](int t) {
        const int k0 = t * 32;
        #pragma unroll
        for (int u = 0; u < 2; u++) {
            const int i = tid + u * 256;
            const int r = i >> 3, c = (i & 7) << 2;
            ra[u] = *(const float4*)(g_ctx + (size_t)(bm + r) * E_ + k0 + c);
            rb[u] = *(const float4*)(Wo + (size_t)(bn + r) * E_ + k0 + c);
        }
    };
    auto store_smem = [&]() {
        #pragma unroll
        for (int u = 0; u < 2; u++) {
            const int i = tid + u * 256;
            const int r = i >> 3, c = (i & 7) << 2;
            split4_store(&sAh[r * 40 + c], &sAl[r * 40 + c], ra[u]);
            split4_store(&sBh[r * 40 + c], &sBl[r * 40 + c], rb[u]);
        }
    };

    ldrs(0);
    for (int t = 0; t < 24; ++t) {
        store_smem();
        __syncthreads();
        if (t + 1 < 24) ldrs(t + 1);
        #pragma unroll
        for (int ks = 0; ks < 2; ks++) {
            wmma::fragment<wmma::matrix_a, 16, 16, 16, __nv_bfloat16, wmma::row_major> ah[2], al[2];
            wmma::fragment<wmma::matrix_b, 16, 16, 16, __nv_bfloat16, wmma::col_major> bh, bl;
            #pragma unroll
            for (int i = 0; i < 2; i++) {
                wmma::load_matrix_sync(ah[i], &sAh[(wm * 32 + i * 16) * 40 + ks * 16], 40);
                wmma::load_matrix_sync(al[i], &sAl[(wm * 32 + i * 16) * 40 + ks * 16], 40);
            }
            wmma::load_matrix_sync(bh, &sBh[(wn * 16) * 40 + ks * 16], 40);
            wmma::load_matrix_sync(bl, &sBl[(wn * 16) * 40 + ks * 16], 40);
            #pragma unroll
            for (int i = 0; i < 2; i++) {
                wmma::mma_sync(acc[i], ah[i], bh, acc[i]);
                wmma::mma_sync(acc[i], ah[i], bl, acc[i]);
                wmma::mma_sync(acc[i], al[i], bh, acc[i]);
            }
        }
        __syncthreads();
    }

    #pragma unroll
    for (int i = 0; i < 2; i++)
        wmma::store_matrix_sync(
            out + (size_t)(bm + wm * 32 + i * 16) * E_ + bn + wn * 16,
            acc[i], E_, wmma::mem_row_major);
}

// ==================== WMMA rotation kernel ====================
// D[192, 8192] = A[192, 8192] @ R[8192, 8192]
// CTA tile 96(M) x 64(N), BK=32.  grid (128 n-tiles, 2 m-tiles), 256 threads,
// 8 warps (2m x 4n), warp tile 48x16.  24.0 KB smem -> 2 CTAs/SM.
// A pre-split bf16 hi/lo; R converted fp32->hi/lo on the fly.
// Register-prefetch pipeline: loads for chunk t+1 issue before MMAs of chunk t.
#define RBK 32
#define RBN 64
#define RNCH (SD_ / RBK)      // 256 chunks
#define RA_LDM 40
#define RB_LDM 72

__global__ void __launch_bounds__(256, 2)
rot_wmma_kernel(const float* __restrict__ R)
{
    __shared__ __nv_bfloat16 sAh[96 * RA_LDM], sAl[96 * RA_LDM];
    __shared__ __nv_bfloat16 sBh[RBK * RB_LDM], sBl[RBK * RB_LDM];

    const int tid = threadIdx.x;
    const int wid = tid >> 5;
    const int wm  = wid >> 2;       // 0..1 -> m offset wm*48
    const int wn  = wid & 3;        // 0..3 -> n offset wn*16
    const int n0  = blockIdx.x * RBN;
    const int m0  = blockIdx.y * 96;

    wmma::fragment<wmma::accumulator, 16, 16, 16, float> acc[3];
    #pragma unroll
    for (int i = 0; i < 3; i++) wmma::fill_fragment(acc[i], 0.0f);

    uint2 pah[3], pal[3];
    float4 prb[2];
    auto ldrs = [&](int t) {
        const int k0 = t * RBK;
        #pragma unroll
        for (int u = 0; u < 3; u++) {
            const int i = tid + u * 256;          // 0..767 : 96 rows x 8 uint2
            const int r = i >> 3, c = (i & 7) << 2;
            pah[u] = *(const uint2*)(g_qa_hi + (size_t)(m0 + r) * SD_ + k0 + c);
            pal[u] = *(const uint2*)(g_qa_lo + (size_t)(m0 + r) * SD_ + k0 + c);
        }
        #pragma unroll
        for (int u = 0; u < 2; u++) {
            const int i = tid + u * 256;          // 0..511 : 32 k-rows x 16 float4
            const int kk = i >> 4, n4 = (i & 15) << 2;
            prb[u] = *(const float4*)(R + (size_t)(k0 + kk) * SD_ + n0 + n4);
        }
    };
    auto store_smem = [&]() {
        #pragma unroll
        for (int u = 0; u < 3; u++) {
            const int i = tid + u * 256;
            const int r = i >> 3, c = (i & 7) << 2;
            *(uint2*)&sAh[r * RA_LDM + c] = pah[u];
            *(uint2*)&sAl[r * RA_LDM + c] = pal[u];
        }
        #pragma unroll
        for (int u = 0; u < 2; u++) {
            const int i = tid + u * 256;
            const int kk = i >> 4, n4 = (i & 15) << 2;
            split4_store(&sBh[kk * RB_LDM + n4], &sBl[kk * RB_LDM + n4], prb[u]);
        }
    };

    ldrs(0);
    for (int t = 0; t < RNCH; ++t) {
        store_smem();
        __syncthreads();
        if (t + 1 < RNCH) ldrs(t + 1);

        #pragma unroll
        for (int ks = 0; ks < 2; ks++) {
            wmma::fragment<wmma::matrix_a, 16, 16, 16, __nv_bfloat16, wmma::row_major> ah[3], al[3];
            wmma::fragment<wmma::matrix_b, 16, 16, 16, __nv_bfloat16, wmma::row_major> bh, bl;
            #pragma unroll
            for (int i = 0; i < 3; i++) {
                wmma::load_matrix_sync(ah[i], &sAh[(wm * 48 + i * 16) * RA_LDM + ks * 16], RA_LDM);
                wmma::load_matrix_sync(al[i], &sAl[(wm * 48 + i * 16) * RA_LDM + ks * 16], RA_LDM);
            }
            wmma::load_matrix_sync(bh, &sBh[(ks * 16) * RB_LDM + wn * 16], RB_LDM);
            wmma::load_matrix_sync(bl, &sBl[(ks * 16) * RB_LDM + wn * 16], RB_LDM);
            #pragma unroll
            for (int i = 0; i < 3; i++) {
                wmma::mma_sync(acc[i], ah[i], bh, acc[i]);
                wmma::mma_sync(acc[i], ah[i], bl, acc[i]);
                wmma::mma_sync(acc[i], al[i], bh, acc[i]);
            }
        }
        __syncthreads();
    }

    #pragma unroll
    for (int i = 0; i < 3; i++)
        wmma::store_matrix_sync(
            g_qkr + (size_t)(m0 + wm * 48 + i * 16) * SD_ + n0 + wn * 16,
            acc[i], SD_, wmma::mem_row_major);
}

// ==================== per-(b,s) head-axis attention ====================
#define ATTN_THREADS 192
__global__ void __launch_bounds__(ATTN_THREADS)
attn_kernel(const float* __restrict__ mask,
            float* __restrict__ attn_out,
            int write_attn)
{
    const int bs = blockIdx.x;
    const int b  = bs >> 7;
    const int s  = bs & 127;
    const int tid = threadIdx.x;

    __shared__ float qs[H_ * D_];
    __shared__ float ks[H_ * D_];
    __shared__ float vs[H_ * D_];
    __shared__ float aw[H_ * H_];

    for (int i = tid; i < H_ * D_; i += ATTN_THREADS) {
        const int h = i >> 6, d = i & 63;
        qs[i] = g_qkr[(((size_t)(b * H_ + h)) << 13) + s * D_ + d];
        ks[i] = g_qkr[(((size_t)(96 + b * H_ + h)) << 13) + s * D_ + d];
        vs[i] = g_v[(size_t)bs * E_ + i];
    }
    __syncthreads();

    if (tid < H_ * H_) {
        const int h = tid / H_, g = tid % H_;
        float acc = 0.0f;
        #pragma unroll
        for (int d = 0; d < D_; d++) acc += qs[h * D_ + d] * ks[g * D_ + d];
        aw[tid] = acc * 0.125f + mask[b * (H_ * H_) + tid];
    }
    __syncthreads();

    if (tid < H_) {
        float mx = -3.0e38f;
        #pragma unroll
        for (int g = 0; g < H_; g++) mx = fmaxf(mx, aw[tid * H_ + g]);
        float e[H_];
        float sum = 0.0f;
        #pragma unroll
        for (int g = 0; g < H_; g++) { e[g] = expf(aw[tid * H_ + g] - mx); sum += e[g]; }
        const float inv = 1.0f / sum;
        #pragma unroll
        for (int g = 0; g < H_; g++) aw[tid * H_ + g] = e[g] * inv;
    }
    __syncthreads();

    if (write_attn && tid < H_ * H_)
        attn_out[(size_t)bs * (H_ * H_) + tid] = aw[tid];

    for (int i = tid; i < H_ * D_; i += ATTN_THREADS) {
        const int h = i >> 6, d = i & 63;
        float acc = 0.0f;
        #pragma unroll
        for (int g = 0; g < H_; g++) acc += aw[h * H_ + g] * vs[g * D_ + d];
        g_ctx[(size_t)b * (H_ * S_ * D_) + h * (S_ * D_) + s * D_ + d] = acc;
    }
}

// ---------------- launch ----------------
extern "C" void kernel_launch(void* const* d_in, const int* in_sizes, int n_in,
                              void* d_out, int out_size)
{
    const float* hidden = (const float*)d_in[0];
    const float* R      = (const float*)d_in[1];
    const float* mask   = (const float*)d_in[2];
    const float* Wq     = (const float*)d_in[3];
    const float* Wk     = (const float*)d_in[4];
    const float* Wv     = (const float*)d_in[5];
    const float* Wo     = (const float*)d_in[6];
    float* out = (float*)d_out;

    const int OUT_ELEMS  = B_ * S_ * E_;
    const int ATTN_ELEMS = B_ * S_ * H_ * H_;
    const int write_attn = (out_size >= OUT_ELEMS + ATTN_ELEMS) ? 1 : 0;

    // 1) WMMA QKV projections, 64x64 tiles, 2 CTAs/SM (q,k -> split rotated layout; v -> g_v)
    wproj_kernel<<<dim3(E_ / 64, BSROWS / 64, 3), 256>>>(hidden, Wq, Wk, Wv);

    // 2) WMMA rotation: 96x64 tiles, 256 CTAs, 2 CTAs/SM, register-prefetch pipeline
    rot_wmma_kernel<<<dim3(SD_ / RBN, 2), 256>>>(R);

    // 3) per-position head-axis attention
    attn_kernel<<<BSROWS, ATTN_THREADS>>>(mask, out + OUT_ELEMS, write_attn);

    // 4) WMMA output projection -> d_out
    wfinal_kernel<<<dim3(E_ / 64, BSROWS / 64), 256>>>(Wo, out);
}